// round 12
// baseline (speedup 1.0000x reference)
#include <cuda_runtime.h>
#include <cuda_bf16.h>

// Problem dims
#define TSTEPS 499
#define BDIM 64
#define NDIM 512
#define DDIM 100
#define ODIM 10
#define KCAT 1536

// RNN kernel config
#define NTHR 512            // 16 warps = 8 k-pairs x 2 b-halves
#define SETUP_THR 256
#define NCTA 128
#define NPAIR 8
#define KSLICE 192          // k per pair (8 pairs x 192 = 1536)
#define SUBK 16             // k per sub-chunk (1024 boundary at pair5 sub4: aligned)
#define NSUB 12
#define DEPTH 4
#define RS_WARP (SUBK * 32)       // warp-private chunk: 16 k x 32 b = 512 floats (2KB)

// Weight SMEM strides (floats), %32==8 -> 4 col slices on distinct bank groups
#define WM1_STRIDE 1544
#define WPMD_STRIDE 1032
#define WS1_STRIDE 520
// partials: [8 pairs][64 b][13] (12 used: m1 c0..3 | pmd c0..3 | s1 c0..3)
#define PROW 13
#define PPLANE (BDIM * PROW)
// W_out smem stride for output phase (reuses partials area)
#define WOS 520

// ---------------- device scratch (static; no allocations) ----------------
__device__ float g_U[2][TSTEPS][BDIM][NDIM];   // [0]=pmd drive, [1]=s1 drive (bias folded)
__device__ float g_r[2][KCAT][BDIM];           // ping-pong rcat, k-major [k][b]
__device__ float g_rm1h[TSTEPS][BDIM][NDIM];   // r_m1 history for deferred output GEMM
__device__ unsigned g_gen;
__device__ unsigned g_count;

// ---------------- setup: init fold + time-parallel input projections ----------------
__global__ void setup_kernel(const float* __restrict__ X,
                             const float* __restrict__ W_in_pmd,
                             const float* __restrict__ W_in_s1,
                             const float* __restrict__ b_pmd,
                             const float* __restrict__ b_s1) {
  __shared__ __align__(16) float Xs[32][DDIM];
  __shared__ __align__(16) float Ws[64][DDIM];
  const int tIdx = blockIdx.x;
  const int y    = blockIdx.y;
  const int tid  = threadIdx.x;

  // folded init (rnn_kernel launches after this kernel completes)
  if (y == 0) {
    if (tIdx == 0 && tid == 0) { g_gen = 0u; g_count = 0u; }
    if (tIdx < 96) {
      float* r0 = &g_r[0][0][0];  // 98304 floats / 96 blocks = 1024 each
      int base = tIdx * 1024;
#pragma unroll
      for (int j = 0; j < 4; j++) r0[base + tid + j * SETUP_THR] = 0.0f;
    }
  }

  const int reg   = y >> 4;
  const int bhalf = (y >> 3) & 1;
  const int nblk  = y & 7;
  const int b0 = bhalf * 32;
  const int n0 = nblk * 64;
  const float* W    = reg ? W_in_s1 : W_in_pmd;
  const float* bias = reg ? b_s1    : b_pmd;
  const float* Xt = X + (size_t)(tIdx + 1) * (BDIM * DDIM);

  for (int i = tid; i < 32 * DDIM; i += SETUP_THR)
    Xs[i / DDIM][i % DDIM] = Xt[(b0 + i / DDIM) * DDIM + (i % DDIM)];
  for (int i = tid; i < 64 * DDIM; i += SETUP_THR)
    Ws[i / DDIM][i % DDIM] = W[(n0 + i / DDIM) * DDIM + (i % DDIM)];
  __syncthreads();

  const int ty = tid >> 4, tx = tid & 15;
  const int bb = 2 * ty, nn = 4 * tx;
  float acc[2][4];
#pragma unroll
  for (int j = 0; j < 4; j++) {
    float bv = bias[n0 + nn + j];
    acc[0][j] = bv; acc[1][j] = bv;
  }
#pragma unroll
  for (int k = 0; k < DDIM; k += 4) {
    float4 x0 = *(const float4*)&Xs[bb][k];
    float4 x1 = *(const float4*)&Xs[bb + 1][k];
#pragma unroll
    for (int j = 0; j < 4; j++) {
      float4 wv = *(const float4*)&Ws[nn + j][k];
      acc[0][j] += x0.x * wv.x + x0.y * wv.y + x0.z * wv.z + x0.w * wv.w;
      acc[1][j] += x1.x * wv.x + x1.y * wv.y + x1.z * wv.z + x1.w * wv.w;
    }
  }
#pragma unroll
  for (int i2 = 0; i2 < 2; i2++)
#pragma unroll
    for (int j = 0; j < 4; j++)
      g_U[reg][tIdx][b0 + bb + i2][n0 + nn + j] = acc[i2][j];
}

// ---------------- persistent serial RNN core (+ fused output projection) ----------------
// copy 16 k-rows x 32 b (2KB); src = rprev + k0*64 + half*32 (row stride 64 floats)
__device__ __forceinline__ void cp_half(float* dst, const float* src, int lane) {
#pragma unroll
  for (int j = 0; j < 4; j++) {
    int seg = lane + j * 32;            // 0..127 16B segments
    int row = seg >> 3;                 // 8 segments per 128B row
    int off = (seg & 7) * 4;
    unsigned s = (unsigned)__cvta_generic_to_shared(dst + seg * 4);
    asm volatile("cp.async.cg.shared.global [%0], [%1], 16;\n"
                 :: "r"(s), "l"(src + row * BDIM + off) : "memory");
  }
}

// r float4 spans 4 b-rows; weight float4 spans 4 k
#define FMA_B(R, W1, W2, AO)                                   \
  am[0] = fmaf(R.x, W1, am[0]); am[1] = fmaf(R.y, W1, am[1]);  \
  am[2] = fmaf(R.z, W1, am[2]); am[3] = fmaf(R.w, W1, am[3]);  \
  AO[0] = fmaf(R.x, W2, AO[0]); AO[1] = fmaf(R.y, W2, AO[1]);  \
  AO[2] = fmaf(R.z, W2, AO[2]); AO[3] = fmaf(R.w, W2, AO[3]);

#define INNER(AO, W2P)                                         \
  _Pragma("unroll")                                            \
  for (int kk = 0; kk < SUBK; kk += 4) {                       \
    float4 wv1 = *(const float4*)(w1 + kk);                    \
    float4 wv2 = *(const float4*)((W2P) + kk);                 \
    float4 r0 = *(const float4*)(rsc + (kk + 0) * 32 + bg4);   \
    float4 r1 = *(const float4*)(rsc + (kk + 1) * 32 + bg4);   \
    float4 r2 = *(const float4*)(rsc + (kk + 2) * 32 + bg4);   \
    float4 r3 = *(const float4*)(rsc + (kk + 3) * 32 + bg4);   \
    FMA_B(r0, wv1.x, wv2.x, AO)                                \
    FMA_B(r1, wv1.y, wv2.y, AO)                                \
    FMA_B(r2, wv1.z, wv2.z, AO)                                \
    FMA_B(r3, wv1.w, wv2.w, AO)                                \
  }

extern __shared__ float s_mem[];

__global__ void __launch_bounds__(NTHR, 1)
rnn_kernel(const float* __restrict__ W_rec_m1,
           const float* __restrict__ W_rec_pmd,
           const float* __restrict__ W_rec_s1,
           const float* __restrict__ b_m1,
           const float* __restrict__ W_pmd_m1,
           const float* __restrict__ W_s1_m1,
           const float* __restrict__ W_m1_pmd,
           const float* __restrict__ W_out,
           float* __restrict__ out) {
  float* wm1  = s_mem;                       // [4][WM1_STRIDE]  vk: rec_m1 | pmd_m1 | s1_m1
  float* wpmd = wm1 + 4 * WM1_STRIDE;        // [4][WPMD_STRIDE] vk: m1_pmd | rec_pmd
  float* ws1  = wpmd + 4 * WPMD_STRIDE;      // [4][WS1_STRIDE]  vk: rec_s1
  float* rs   = ws1 + 4 * WS1_STRIDE;        // [16 warps][DEPTH][SUBK][32]
  float* part = rs + 16 * DEPTH * RS_WARP;   // [8 pairs][64 b][PROW]

  const int cta = blockIdx.x;
  const int tid = threadIdx.x;
  const int nbase = cta * 4;

  // cache this CTA's weight column slices in SMEM for the whole run
  for (int i = tid; i < 4 * NDIM; i += NTHR) {
    int slot = i >> 9;
    int k = i & 511;
    int n = nbase + slot;
    wm1[slot * WM1_STRIDE + k]          = W_rec_m1[n * NDIM + k];
    wm1[slot * WM1_STRIDE + 512 + k]    = W_pmd_m1[n * NDIM + k];
    wm1[slot * WM1_STRIDE + 1024 + k]   = W_s1_m1[n * NDIM + k];
    wpmd[slot * WPMD_STRIDE + k]        = W_m1_pmd[n * NDIM + k];
    wpmd[slot * WPMD_STRIDE + 512 + k]  = W_rec_pmd[n * NDIM + k];
    ws1[slot * WS1_STRIDE + k]          = W_rec_s1[n * NDIM + k];
  }

  // compute-role mapping: warp = (pair, b-half); lane = (bg, col)
  const int warp = tid >> 5;
  const int lane = tid & 31;
  const int pair = warp >> 1;
  const int half = warp & 1;
  const int bg4 = (lane >> 2) * 4;          // 0..28: 4-row group within the 32-b half
  const int cg  = lane & 3;                 // column slot 0..3
  const int kbase = pair * KSLICE;
  const int srcoff = half * 32;             // b offset of this warp's half
  float* rs_w = rs + warp * DEPTH * RS_WARP;

  // state-role mapping (first 256 threads): thread owns cell (b, col)
  const int b = tid >> 2;
  const int slot = tid & 3;
  const int col = nbase + slot;
  const float bias_m1 = (tid < 256) ? b_m1[col] : 0.0f;
  const float a = 0.1f;
  const float oma = 1.0f - a;
  float x_m1 = 0.0f, x_pmd = 0.0f, x_s1 = 0.0f;
  __syncthreads();

  for (int t = 1; t <= TSTEPS; t++) {
    float u_pmd = 0.f, u_s1 = 0.f;
    if (tid < 256) {
      u_pmd = __ldg(&g_U[0][t - 1][b][col]);
      u_s1  = __ldg(&g_U[1][t - 1][b][col]);
    }

    const float* rprev = &g_r[(t - 1) & 1][0][0];   // [k][b]
    const float* src0 = rprev + (size_t)kbase * BDIM + srcoff;

    // prime 3 chunks (warp-private depth-4 pipeline; no CTA syncs in mainloop)
#pragma unroll
    for (int p = 0; p < 3; p++) {
      cp_half(rs_w + p * RS_WARP, src0 + (size_t)(p * SUBK) * BDIM, lane);
      asm volatile("cp.async.commit_group;\n" ::: "memory");
    }

    float am[4]  = {0.f, 0.f, 0.f, 0.f};   // m1 over 4 b-rows
    float ap[4]  = {0.f, 0.f, 0.f, 0.f};   // pmd
    float as_[4] = {0.f, 0.f, 0.f, 0.f};   // s1

#pragma unroll 1
    for (int s = 0; s < NSUB; s++) {
      const int rem = NSUB - 1 - s;       // chunks still outstanding beyond s
      if (rem >= 3)      { asm volatile("cp.async.wait_group 2;\n" ::: "memory"); }
      else if (rem == 2) { asm volatile("cp.async.wait_group 2;\n" ::: "memory"); }
      else if (rem == 1) { asm volatile("cp.async.wait_group 1;\n" ::: "memory"); }
      else               { asm volatile("cp.async.wait_group 0;\n" ::: "memory"); }

      const int k0 = kbase + s * SUBK;
      const float* rsc = rs_w + (s & 3) * RS_WARP;
      const float* w1 = wm1 + cg * WM1_STRIDE + k0;
      if (k0 < 1024) {   // sub-chunks never straddle the 1024 boundary
        const float* w2 = wpmd + cg * WPMD_STRIDE + k0;
        INNER(ap, w2)
      } else {
        const float* w2 = ws1 + cg * WS1_STRIDE + (k0 - 1024);
        INNER(as_, w2)
      }
      if (s + 3 < NSUB) {
        cp_half(rs_w + ((s + 3) & 3) * RS_WARP, src0 + (size_t)((s + 3) * SUBK) * BDIM, lane);
        asm volatile("cp.async.commit_group;\n" ::: "memory");
      }
    }

    // write k-pair partials
    {
      float* p0 = part + pair * PPLANE + (srcoff + bg4) * PROW;
#pragma unroll
      for (int row = 0; row < 4; row++) {
        float* p = p0 + row * PROW;
        p[cg] = am[row]; p[4 + cg] = ap[row]; p[8 + cg] = as_[row];
      }
    }
    __syncthreads();

    // reduce over 8 k-pairs + leaky update + tanh (state role: first 256 threads)
    if (tid < 256) {
      float sm = 0.f, sp = 0.f, ss = 0.f;
#pragma unroll
      for (int q = 0; q < NPAIR; q++) {
        const float* p = part + q * PPLANE + b * PROW;
        sm += p[slot]; sp += p[4 + slot]; ss += p[8 + slot];
      }
      x_m1  = oma * x_m1  + a * (sm + bias_m1);
      x_pmd = oma * x_pmd + a * (sp + u_pmd);
      x_s1  = oma * x_s1  + a * (ss + u_s1);
      const float r_m1  = tanhf(x_m1);
      const float r_pmd = tanhf(x_pmd);
      const float r_s1v = tanhf(x_s1);

      float* rn = &g_r[t & 1][0][0];
      rn[col * BDIM + b]          = r_m1;
      rn[(512 + col) * BDIM + b]  = r_pmd;
      rn[(1024 + col) * BDIM + b] = r_s1v;
      g_rm1h[t - 1][b][col] = r_m1;
    }

    // ---- grid barrier (monotone generation; all 128 CTAs resident) ----
    __threadfence();
    __syncthreads();
    if (tid == 0) {
      unsigned prev = atomicAdd(&g_count, 1u);
      if (prev == (unsigned)NCTA * (unsigned)t - 1u) {
        __threadfence();
        *((volatile unsigned*)&g_gen) = (unsigned)t;
      } else {
        while (*((volatile unsigned*)&g_gen) < (unsigned)t) { }
        __threadfence();
      }
    }
    __syncthreads();
  }

  // ---------------- fused output projection: out[t] = r_m1[t] @ W_out^T ----------------
  float* wo = part;   // reuse partials area: ODIM*WOS = 5200 <= 6656 floats
  for (int i = tid; i < ODIM * NDIM; i += NTHR)
    wo[(i / NDIM) * WOS + (i % NDIM)] = W_out[i];
  __syncthreads();

  for (int t = cta; t < TSTEPS; t += NCTA) {
    const float* R = &g_rm1h[t][0][0];
    for (int idx = tid; idx < BDIM * ODIM; idx += NTHR) {
      int bb = idx / ODIM, o = idx % ODIM;
      const float* r = R + bb * NDIM;
      const float* w = wo + o * WOS;
      float s0 = 0.f, s1 = 0.f, s2 = 0.f, s3 = 0.f;
#pragma unroll 8
      for (int k = 0; k < NDIM; k += 16) {
        float4 r0 = *(const float4*)(r + k);
        float4 r1 = *(const float4*)(r + k + 4);
        float4 r2 = *(const float4*)(r + k + 8);
        float4 r3 = *(const float4*)(r + k + 12);
        float4 w0 = *(const float4*)(w + k);
        float4 w1 = *(const float4*)(w + k + 4);
        float4 w2 = *(const float4*)(w + k + 8);
        float4 w3 = *(const float4*)(w + k + 12);
        s0 += r0.x * w0.x + r0.y * w0.y + r0.z * w0.z + r0.w * w0.w;
        s1 += r1.x * w1.x + r1.y * w1.y + r1.z * w1.z + r1.w * w1.w;
        s2 += r2.x * w2.x + r2.y * w2.y + r2.z * w2.z + r2.w * w2.w;
        s3 += r3.x * w3.x + r3.y * w3.y + r3.z * w3.z + r3.w * w3.w;
      }
      out[t * (BDIM * ODIM) + idx] = (s0 + s1) + (s2 + s3);
    }
  }
}

// ---------------- launch ----------------
extern "C" void kernel_launch(void* const* d_in, const int* in_sizes, int n_in,
                              void* d_out, int out_size) {
  (void)in_sizes; (void)n_in; (void)out_size;
  const float* X         = (const float*)d_in[0];
  const float* W_rec_m1  = (const float*)d_in[1];
  const float* W_rec_pmd = (const float*)d_in[2];
  const float* W_rec_s1  = (const float*)d_in[3];
  const float* b_m1      = (const float*)d_in[4];
  const float* b_pmd     = (const float*)d_in[5];
  const float* b_s1      = (const float*)d_in[6];
  const float* W_pmd_m1  = (const float*)d_in[7];
  const float* W_s1_m1   = (const float*)d_in[8];
  const float* W_m1_pmd  = (const float*)d_in[9];
  const float* W_in_pmd  = (const float*)d_in[10];
  const float* W_in_s1   = (const float*)d_in[11];
  const float* W_out     = (const float*)d_in[12];
  float* out = (float*)d_out;

  dim3 gA(TSTEPS, 32);
  setup_kernel<<<gA, SETUP_THR>>>(X, W_in_pmd, W_in_s1, b_pmd, b_s1);

  const int smem_bytes =
      (4 * WM1_STRIDE + 4 * WPMD_STRIDE + 4 * WS1_STRIDE +
       16 * DEPTH * RS_WARP + NPAIR * PPLANE) * (int)sizeof(float);   // 207,232 B
  cudaFuncSetAttribute(rnn_kernel, cudaFuncAttributeMaxDynamicSharedMemorySize, smem_bytes);
  rnn_kernel<<<NCTA, NTHR, smem_bytes>>>(W_rec_m1, W_rec_pmd, W_rec_s1, b_m1,
                                         W_pmd_m1, W_s1_m1, W_m1_pmd, W_out, out);
}

// round 14
// speedup vs baseline: 1.0896x; 1.0896x over previous
#include <cuda_runtime.h>
#include <cuda_bf16.h>

// Problem dims
#define TSTEPS 499
#define BDIM 64
#define NDIM 512
#define DDIM 100
#define ODIM 10
#define KCAT 1536

// RNN kernel config
#define NCTA 128
#define NTHR 256
#define KSLICE 192          // virtual-k per warp (8 warps x 192 = 1536)
#define SUBK 32             // k per sub-chunk (1024 boundary = warp5,sub2 start: aligned)
#define NSUB 6
#define RS_SUB (SUBK * BDIM)      // 2048 floats = 8KB

// SMEM weight strides (floats), %32==8 -> col slices on distinct bank groups
#define WM1_STRIDE 1544
#define WPMD_STRIDE 1032
#define WS1_STRIDE 520
// partials: [8 warps][64 b][13] (12 used: m1 c0..3 | pmd c0..3 | s1 c0..3)
#define PROW 13
#define PPLANE (BDIM * PROW)
// W_out smem stride for output phase (reuses partials area)
#define WOS 520

// tree barrier: 8 groups of 16 CTAs; counters spread 256B to dodge L2 hash pairing
#define NGRP 8
#define GRP_STRIDE 64       // unsigneds = 256B

// ---------------- device scratch (static; no allocations) ----------------
__device__ float g_U[2][TSTEPS][BDIM][NDIM];   // [0]=pmd drive, [1]=s1 drive (bias folded)
__device__ float g_r[2][KCAT][BDIM];           // ping-pong rcat, k-major [k][b]
__device__ float g_rm1h[TSTEPS][BDIM][NDIM];   // r_m1 history for deferred output GEMM
__device__ unsigned g_gcnt[NGRP * GRP_STRIDE]; // group arrival counters (monotone)
__device__ unsigned g_root;                    // root arrival counter (monotone)
__device__ unsigned g_gen;                     // release generation

// ---------------- setup: init fold + time-parallel input projections ----------------
__global__ void setup_kernel(const float* __restrict__ X,
                             const float* __restrict__ W_in_pmd,
                             const float* __restrict__ W_in_s1,
                             const float* __restrict__ b_pmd,
                             const float* __restrict__ b_s1) {
  __shared__ __align__(16) float Xs[32][DDIM];
  __shared__ __align__(16) float Ws[64][DDIM];
  const int tIdx = blockIdx.x;
  const int y    = blockIdx.y;
  const int tid  = threadIdx.x;

  // folded init (rnn_kernel launches after this kernel completes)
  if (y == 0) {
    if (tIdx == 0 && tid == 0) {
      g_gen = 0u; g_root = 0u;
#pragma unroll
      for (int g = 0; g < NGRP; g++) g_gcnt[g * GRP_STRIDE] = 0u;
    }
    if (tIdx < 96) {
      float* r0 = &g_r[0][0][0];  // 98304 floats / 96 blocks = 1024 each
      int base = tIdx * 1024;
#pragma unroll
      for (int j = 0; j < 4; j++) r0[base + tid + j * NTHR] = 0.0f;
    }
  }

  const int reg   = y >> 4;
  const int bhalf = (y >> 3) & 1;
  const int nblk  = y & 7;
  const int b0 = bhalf * 32;
  const int n0 = nblk * 64;
  const float* W    = reg ? W_in_s1 : W_in_pmd;
  const float* bias = reg ? b_s1    : b_pmd;
  const float* Xt = X + (size_t)(tIdx + 1) * (BDIM * DDIM);

  for (int i = tid; i < 32 * DDIM; i += NTHR)
    Xs[i / DDIM][i % DDIM] = Xt[(b0 + i / DDIM) * DDIM + (i % DDIM)];
  for (int i = tid; i < 64 * DDIM; i += NTHR)
    Ws[i / DDIM][i % DDIM] = W[(n0 + i / DDIM) * DDIM + (i % DDIM)];
  __syncthreads();

  const int ty = tid >> 4, tx = tid & 15;
  const int bb = 2 * ty, nn = 4 * tx;
  float acc[2][4];
#pragma unroll
  for (int j = 0; j < 4; j++) {
    float bv = bias[n0 + nn + j];
    acc[0][j] = bv; acc[1][j] = bv;
  }
#pragma unroll
  for (int k = 0; k < DDIM; k += 4) {
    float4 x0 = *(const float4*)&Xs[bb][k];
    float4 x1 = *(const float4*)&Xs[bb + 1][k];
#pragma unroll
    for (int j = 0; j < 4; j++) {
      float4 wv = *(const float4*)&Ws[nn + j][k];
      acc[0][j] += x0.x * wv.x + x0.y * wv.y + x0.z * wv.z + x0.w * wv.w;
      acc[1][j] += x1.x * wv.x + x1.y * wv.y + x1.z * wv.z + x1.w * wv.w;
    }
  }
#pragma unroll
  for (int i2 = 0; i2 < 2; i2++)
#pragma unroll
    for (int j = 0; j < 4; j++)
      g_U[reg][tIdx][b0 + bb + i2][n0 + nn + j] = acc[i2][j];
}

// ---------------- persistent serial RNN core (+ fused output projection) ----------------
__device__ __forceinline__ void cp_sub(float* dst, const float* src, int lane) {
  // contiguous 8KB (32 k-rows x 64 b) copy, 16 float4 per lane
#pragma unroll
  for (int j = 0; j < 16; j++) {
    int o = (lane + j * 32) * 4;
    unsigned s = (unsigned)__cvta_generic_to_shared(dst + o);
    asm volatile("cp.async.cg.shared.global [%0], [%1], 16;\n" :: "r"(s), "l"(src + o) : "memory");
  }
}

#define FMA_J(R, WA, WB, VA, VB, AO)                                        \
  am[0][0] = fmaf(R.x, WA, am[0][0]); am[1][0] = fmaf(R.y, WA, am[1][0]);   \
  am[2][0] = fmaf(R.z, WA, am[2][0]); am[3][0] = fmaf(R.w, WA, am[3][0]);   \
  am[0][1] = fmaf(R.x, WB, am[0][1]); am[1][1] = fmaf(R.y, WB, am[1][1]);   \
  am[2][1] = fmaf(R.z, WB, am[2][1]); am[3][1] = fmaf(R.w, WB, am[3][1]);   \
  AO[0][0] = fmaf(R.x, VA, AO[0][0]); AO[1][0] = fmaf(R.y, VA, AO[1][0]);   \
  AO[2][0] = fmaf(R.z, VA, AO[2][0]); AO[3][0] = fmaf(R.w, VA, AO[3][0]);   \
  AO[0][1] = fmaf(R.x, VB, AO[0][1]); AO[1][1] = fmaf(R.y, VB, AO[1][1]);   \
  AO[2][1] = fmaf(R.z, VB, AO[2][1]); AO[3][1] = fmaf(R.w, VB, AO[3][1]);

#define INNER(AO, V1, V2)                                                   \
  _Pragma("unroll 4")                                                       \
  for (int kk = 0; kk < SUBK; kk += 4) {                                    \
    float4 r0 = *(const float4*)(rsc + (kk + 0) * BDIM + bg4);              \
    float4 r1 = *(const float4*)(rsc + (kk + 1) * BDIM + bg4);              \
    float4 r2 = *(const float4*)(rsc + (kk + 2) * BDIM + bg4);              \
    float4 r3 = *(const float4*)(rsc + (kk + 3) * BDIM + bg4);              \
    float4 wa = *(const float4*)(w1a + kk);                                 \
    float4 wb = *(const float4*)(w1b + kk);                                 \
    float4 va = *(const float4*)((V1) + kk);                                \
    float4 vb = *(const float4*)((V2) + kk);                                \
    FMA_J(r0, wa.x, wb.x, va.x, vb.x, AO)                                   \
    FMA_J(r1, wa.y, wb.y, va.y, vb.y, AO)                                   \
    FMA_J(r2, wa.z, wb.z, va.z, vb.z, AO)                                   \
    FMA_J(r3, wa.w, wb.w, va.w, vb.w, AO)                                   \
  }

extern __shared__ float s_mem[];

__global__ void __launch_bounds__(NTHR, 1)
rnn_kernel(const float* __restrict__ W_rec_m1,
           const float* __restrict__ W_rec_pmd,
           const float* __restrict__ W_rec_s1,
           const float* __restrict__ b_m1,
           const float* __restrict__ W_pmd_m1,
           const float* __restrict__ W_s1_m1,
           const float* __restrict__ W_m1_pmd,
           const float* __restrict__ W_out,
           float* __restrict__ out) {
  float* wm1  = s_mem;                       // [4][WM1_STRIDE]  vk: rec_m1 | pmd_m1 | s1_m1
  float* wpmd = wm1 + 4 * WM1_STRIDE;        // [4][WPMD_STRIDE] vk: m1_pmd | rec_pmd
  float* ws1  = wpmd + 4 * WPMD_STRIDE;      // [4][WS1_STRIDE]  vk: rec_s1
  float* rs   = ws1 + 4 * WS1_STRIDE;        // [8 warps][2][SUBK][BDIM]
  float* part = rs + 8 * 2 * RS_SUB;         // [8][BDIM][PROW]

  const int cta = blockIdx.x;
  const int tid = threadIdx.x;
  const int nbase = cta * 4;

  // cache this CTA's weight column slices in SMEM for the whole run
  for (int i = tid; i < 4 * NDIM; i += NTHR) {
    int slot = i >> 9;
    int k = i & 511;
    int n = nbase + slot;
    wm1[slot * WM1_STRIDE + k]          = W_rec_m1[n * NDIM + k];
    wm1[slot * WM1_STRIDE + 512 + k]    = W_pmd_m1[n * NDIM + k];
    wm1[slot * WM1_STRIDE + 1024 + k]   = W_s1_m1[n * NDIM + k];
    wpmd[slot * WPMD_STRIDE + k]        = W_m1_pmd[n * NDIM + k];
    wpmd[slot * WPMD_STRIDE + 512 + k]  = W_rec_pmd[n * NDIM + k];
    ws1[slot * WS1_STRIDE + k]          = W_rec_s1[n * NDIM + k];
  }

  // compute-role mapping: warp owns 192 virtual-k; halves own col pairs; bg owns 4 b-rows
  const int warp = tid >> 5;
  const int lane = tid & 31;
  const int cg = (tid >> 4) & 1;
  const int bg4 = (tid & 15) * 4;
  const int kbase = warp * KSLICE;
  const int ca = cg * 2, cb = cg * 2 + 1;
  float* rs0 = rs + warp * 2 * RS_SUB;

  // state-role mapping: thread owns cell (b, col)
  const int b = tid >> 2;
  const int slot = tid & 3;
  const int col = nbase + slot;
  const float bias_m1 = b_m1[col];
  const float a = 0.1f;
  const float oma = 1.0f - a;
  float x_m1 = 0.0f, x_pmd = 0.0f, x_s1 = 0.0f;
  __syncthreads();

  for (int t = 1; t <= TSTEPS; t++) {
    const float u_pmd = __ldg(&g_U[0][t - 1][b][col]);
    const float u_s1  = __ldg(&g_U[1][t - 1][b][col]);

    const float* rprev = &g_r[(t - 1) & 1][0][0];   // [k][b]

    // prime first two sub-chunks (warp-local double buffer; no CTA syncs in mainloop)
    cp_sub(rs0, rprev + (size_t)kbase * BDIM, lane);
    asm volatile("cp.async.commit_group;\n" ::: "memory");
    cp_sub(rs0 + RS_SUB, rprev + (size_t)(kbase + SUBK) * BDIM, lane);
    asm volatile("cp.async.commit_group;\n" ::: "memory");

    float am[4][2] = {{0.f, 0.f}, {0.f, 0.f}, {0.f, 0.f}, {0.f, 0.f}};
    float ap[4][2] = {{0.f, 0.f}, {0.f, 0.f}, {0.f, 0.f}, {0.f, 0.f}};
    float as_[4][2] = {{0.f, 0.f}, {0.f, 0.f}, {0.f, 0.f}, {0.f, 0.f}};

#pragma unroll 1
    for (int s = 0; s < NSUB; s++) {
      if (s < NSUB - 1) { asm volatile("cp.async.wait_group 1;\n" ::: "memory"); }
      else              { asm volatile("cp.async.wait_group 0;\n" ::: "memory"); }

      const int k0 = kbase + s * SUBK;
      const float* rsc = rs0 + (s & 1) * RS_SUB;
      const float* w1a = wm1 + ca * WM1_STRIDE + k0;
      const float* w1b = wm1 + cb * WM1_STRIDE + k0;
      if (k0 < 1024) {   // sub-chunks never straddle the 1024 boundary
        const float* v1 = wpmd + ca * WPMD_STRIDE + k0;
        const float* v2 = wpmd + cb * WPMD_STRIDE + k0;
        INNER(ap, v1, v2)
      } else {
        const float* v1 = ws1 + ca * WS1_STRIDE + (k0 - 1024);
        const float* v2 = ws1 + cb * WS1_STRIDE + (k0 - 1024);
        INNER(as_, v1, v2)
      }
      if (s + 2 < NSUB) {
        cp_sub(rs0 + (s & 1) * RS_SUB, rprev + (size_t)(k0 + 2 * SUBK) * BDIM, lane);
        asm volatile("cp.async.commit_group;\n" ::: "memory");
      }
    }

    // write k-slice partials
    {
      float* p0 = part + warp * PPLANE + bg4 * PROW;
#pragma unroll
      for (int row = 0; row < 4; row++) {
        float* p = p0 + row * PROW;
        p[ca]     = am[row][0];  p[cb]     = am[row][1];
        p[4 + ca] = ap[row][0];  p[4 + cb] = ap[row][1];
        p[8 + ca] = as_[row][0]; p[8 + cb] = as_[row][1];
      }
    }
    __syncthreads();

    // reduce over 8 k-slices + leaky update + tanh (state role)
    float sm = 0.f, sp = 0.f, ss = 0.f;
#pragma unroll
    for (int q = 0; q < 8; q++) {
      const float* p = part + q * PPLANE + b * PROW;
      sm += p[slot]; sp += p[4 + slot]; ss += p[8 + slot];
    }
    x_m1  = oma * x_m1  + a * (sm + bias_m1);
    x_pmd = oma * x_pmd + a * (sp + u_pmd);
    x_s1  = oma * x_s1  + a * (ss + u_s1);
    const float r_m1  = tanhf(x_m1);
    const float r_pmd = tanhf(x_pmd);
    const float r_s1v = tanhf(x_s1);

    float* rn = &g_r[t & 1][0][0];
    rn[col * BDIM + b]          = r_m1;
    rn[(512 + col) * BDIM + b]  = r_pmd;
    rn[(1024 + col) * BDIM + b] = r_s1v;
    g_rm1h[t - 1][b][col] = r_m1;

    // ---- tree grid barrier (monotone counters; all 128 CTAs resident) ----
    // level 1: 8 groups of 16 CTAs on 256B-spread counters (parallel LTS ALUs)
    // level 2: group leaders hit the root; 8th root arriver releases g_gen = t.
    __threadfence();
    __syncthreads();
    if (tid == 0) {
      unsigned gprev = atomicAdd(&g_gcnt[(cta >> 4) * GRP_STRIDE], 1u);
      if (gprev == 16u * (unsigned)t - 1u) {
        unsigned rprev_ = atomicAdd(&g_root, 1u);
        if (rprev_ == (unsigned)NGRP * (unsigned)t - 1u) {
          __threadfence();
          *((volatile unsigned*)&g_gen) = (unsigned)t;
        } else {
          while (*((volatile unsigned*)&g_gen) < (unsigned)t) { }
          __threadfence();
        }
      } else {
        while (*((volatile unsigned*)&g_gen) < (unsigned)t) { }
        __threadfence();
      }
    }
    __syncthreads();
  }

  // ---------------- fused output projection: out[t] = r_m1[t] @ W_out^T ----------------
  float* wo = part;   // reuse partials area: ODIM*WOS = 5200 <= 6656 floats
  for (int i = tid; i < ODIM * NDIM; i += NTHR)
    wo[(i / NDIM) * WOS + (i % NDIM)] = W_out[i];
  __syncthreads();

  for (int t = cta; t < TSTEPS; t += NCTA) {
    const float* R = &g_rm1h[t][0][0];
    for (int idx = tid; idx < BDIM * ODIM; idx += NTHR) {
      int bb = idx / ODIM, o = idx % ODIM;
      const float* r = R + bb * NDIM;
      const float* w = wo + o * WOS;
      float s0 = 0.f, s1 = 0.f, s2 = 0.f, s3 = 0.f;
#pragma unroll 8
      for (int k = 0; k < NDIM; k += 16) {
        float4 r0 = *(const float4*)(r + k);
        float4 r1 = *(const float4*)(r + k + 4);
        float4 r2 = *(const float4*)(r + k + 8);
        float4 r3 = *(const float4*)(r + k + 12);
        float4 w0 = *(const float4*)(w + k);
        float4 w1 = *(const float4*)(w + k + 4);
        float4 w2 = *(const float4*)(w + k + 8);
        float4 w3 = *(const float4*)(w + k + 12);
        s0 += r0.x * w0.x + r0.y * w0.y + r0.z * w0.z + r0.w * w0.w;
        s1 += r1.x * w1.x + r1.y * w1.y + r1.z * w1.z + r1.w * w1.w;
        s2 += r2.x * w2.x + r2.y * w2.y + r2.z * w2.z + r2.w * w2.w;
        s3 += r3.x * w3.x + r3.y * w3.y + r3.z * w3.z + r3.w * w3.w;
      }
      out[t * (BDIM * ODIM) + idx] = (s0 + s1) + (s2 + s3);
    }
  }
}

// ---------------- launch ----------------
extern "C" void kernel_launch(void* const* d_in, const int* in_sizes, int n_in,
                              void* d_out, int out_size) {
  (void)in_sizes; (void)n_in; (void)out_size;
  const float* X         = (const float*)d_in[0];
  const float* W_rec_m1  = (const float*)d_in[1];
  const float* W_rec_pmd = (const float*)d_in[2];
  const float* W_rec_s1  = (const float*)d_in[3];
  const float* b_m1      = (const float*)d_in[4];
  const float* b_pmd     = (const float*)d_in[5];
  const float* b_s1      = (const float*)d_in[6];
  const float* W_pmd_m1  = (const float*)d_in[7];
  const float* W_s1_m1   = (const float*)d_in[8];
  const float* W_m1_pmd  = (const float*)d_in[9];
  const float* W_in_pmd  = (const float*)d_in[10];
  const float* W_in_s1   = (const float*)d_in[11];
  const float* W_out     = (const float*)d_in[12];
  float* out = (float*)d_out;

  dim3 gA(TSTEPS, 32);
  setup_kernel<<<gA, NTHR>>>(X, W_in_pmd, W_in_s1, b_pmd, b_s1);

  const int smem_bytes =
      (4 * WM1_STRIDE + 4 * WPMD_STRIDE + 4 * WS1_STRIDE + 8 * 2 * RS_SUB + 8 * PPLANE) *
      (int)sizeof(float);   // 207,232 B
  cudaFuncSetAttribute(rnn_kernel, cudaFuncAttributeMaxDynamicSharedMemorySize, smem_bytes);
  rnn_kernel<<<NCTA, NTHR, smem_bytes>>>(W_rec_m1, W_rec_pmd, W_rec_s1, b_m1,
                                         W_pmd_m1, W_s1_m1, W_m1_pmd, W_out, out);
}

// round 15
// speedup vs baseline: 1.2023x; 1.1034x over previous
#include <cuda_runtime.h>
#include <cuda_bf16.h>

// Problem dims
#define TSTEPS 499
#define BDIM 64
#define NDIM 512
#define DDIM 100
#define ODIM 10
#define KCAT 1536

// RNN kernel config
#define NCTA 128
#define NTHR 256
#define KSLICE 192          // virtual-k per warp (8 warps x 192 = 1536)
#define SUBK 32             // k per sub-chunk (region boundaries k=512/1024 are multiples: aligned)
#define NSUB 6
#define RS_SUB (SUBK * BDIM)      // 2048 floats = 8KB

// SMEM weight strides (floats), %32==8 -> col slices on distinct bank groups
#define WM1_STRIDE 1544
#define WPMD_STRIDE 1032
#define WS1_STRIDE 520
// partials: [8 warps][64 b][13] (12 used: m1 c0..3 | pmd c0..3 | s1 c0..3)
#define PROW 13
#define PPLANE (BDIM * PROW)
// W_out smem stride for output phase (reuses partials area)
#define WOS 520

// per-CTA publish flags, spread 256B to distribute poll traffic over LTS partitions
#define FLAG_STRIDE 64      // unsigneds = 256B

// ---------------- device scratch (static; no allocations) ----------------
__device__ float g_U[2][TSTEPS][BDIM][NDIM];   // [0]=pmd drive, [1]=s1 drive (bias folded)
__device__ float g_r[2][KCAT][BDIM];           // ping-pong rcat, k-major [k][b]
__device__ float g_rm1h[TSTEPS][BDIM][NDIM];   // r_m1 history for deferred output GEMM
__device__ unsigned g_flag[NCTA * FLAG_STRIDE];// per-CTA step-publication flags (monotone)
__device__ unsigned g_count;                   // final-barrier arrival counter
__device__ unsigned g_gen;                     // final-barrier release

// ---------------- setup: init fold + time-parallel input projections ----------------
__global__ void setup_kernel(const float* __restrict__ X,
                             const float* __restrict__ W_in_pmd,
                             const float* __restrict__ W_in_s1,
                             const float* __restrict__ b_pmd,
                             const float* __restrict__ b_s1) {
  __shared__ __align__(16) float Xs[32][DDIM];
  __shared__ __align__(16) float Ws[64][DDIM];
  const int tIdx = blockIdx.x;
  const int y    = blockIdx.y;
  const int tid  = threadIdx.x;

  // folded init (rnn_kernel launches after this kernel completes)
  if (y == 0) {
    if (tIdx == 0 && tid == 0) { g_gen = 0u; g_count = 0u; }
    if (tIdx < 96) {
      float* r0 = &g_r[0][0][0];  // 98304 floats / 96 blocks = 1024 each
      int base = tIdx * 1024;
#pragma unroll
      for (int j = 0; j < 4; j++) r0[base + tid + j * NTHR] = 0.0f;
    } else {
      g_flag[(tIdx - 96) * NTHR + tid] = 0u;   // 32 blocks x 256 = 8192 = NCTA*FLAG_STRIDE
    }
  }

  const int reg   = y >> 4;
  const int bhalf = (y >> 3) & 1;
  const int nblk  = y & 7;
  const int b0 = bhalf * 32;
  const int n0 = nblk * 64;
  const float* W    = reg ? W_in_s1 : W_in_pmd;
  const float* bias = reg ? b_s1    : b_pmd;
  const float* Xt = X + (size_t)(tIdx + 1) * (BDIM * DDIM);

  for (int i = tid; i < 32 * DDIM; i += NTHR)
    Xs[i / DDIM][i % DDIM] = Xt[(b0 + i / DDIM) * DDIM + (i % DDIM)];
  for (int i = tid; i < 64 * DDIM; i += NTHR)
    Ws[i / DDIM][i % DDIM] = W[(n0 + i / DDIM) * DDIM + (i % DDIM)];
  __syncthreads();

  const int ty = tid >> 4, tx = tid & 15;
  const int bb = 2 * ty, nn = 4 * tx;
  float acc[2][4];
#pragma unroll
  for (int j = 0; j < 4; j++) {
    float bv = bias[n0 + nn + j];
    acc[0][j] = bv; acc[1][j] = bv;
  }
#pragma unroll
  for (int k = 0; k < DDIM; k += 4) {
    float4 x0 = *(const float4*)&Xs[bb][k];
    float4 x1 = *(const float4*)&Xs[bb + 1][k];
#pragma unroll
    for (int j = 0; j < 4; j++) {
      float4 wv = *(const float4*)&Ws[nn + j][k];
      acc[0][j] += x0.x * wv.x + x0.y * wv.y + x0.z * wv.z + x0.w * wv.w;
      acc[1][j] += x1.x * wv.x + x1.y * wv.y + x1.z * wv.z + x1.w * wv.w;
    }
  }
#pragma unroll
  for (int i2 = 0; i2 < 2; i2++)
#pragma unroll
    for (int j = 0; j < 4; j++)
      g_U[reg][tIdx][b0 + bb + i2][n0 + nn + j] = acc[i2][j];
}

// ---------------- persistent serial RNN core (+ fused output projection) ----------------
__device__ __forceinline__ void cp_sub(float* dst, const float* src, int lane) {
  // contiguous 8KB (32 k-rows x 64 b) copy, 16 float4 per lane; .cg bypasses L1
#pragma unroll
  for (int j = 0; j < 16; j++) {
    int o = (lane + j * 32) * 4;
    unsigned s = (unsigned)__cvta_generic_to_shared(dst + o);
    asm volatile("cp.async.cg.shared.global [%0], [%1], 16;\n" :: "r"(s), "l"(src + o) : "memory");
  }
}

// wait until the 8 producer CTAs of chunk vk0 have published step `need`
__device__ __forceinline__ void wait_prod(int vk0, unsigned need, int lane) {
  if (need == 0u) return;                      // initial state (zeros) always ready
  const int base = (vk0 & 511) >> 2;
  for (;;) {
    unsigned f = need;
    if (lane < 8) f = *(volatile unsigned*)&g_flag[(base + lane) * FLAG_STRIDE];
    if (__all_sync(0xffffffffu, f >= need)) return;
  }
}

// combined wait for the two primed chunks (lanes 0-7: chunk A, lanes 8-15: chunk B)
__device__ __forceinline__ void wait_prod2(int vkA, int vkB, unsigned need, int lane) {
  if (need == 0u) return;
  const int baseA = (vkA & 511) >> 2;
  const int baseB = (vkB & 511) >> 2;
  for (;;) {
    unsigned f = need;
    if (lane < 8)       f = *(volatile unsigned*)&g_flag[(baseA + lane) * FLAG_STRIDE];
    else if (lane < 16) f = *(volatile unsigned*)&g_flag[(baseB + lane - 8) * FLAG_STRIDE];
    if (__all_sync(0xffffffffu, f >= need)) return;
  }
}

#define FMA_J(R, WA, WB, VA, VB, AO)                                        \
  am[0][0] = fmaf(R.x, WA, am[0][0]); am[1][0] = fmaf(R.y, WA, am[1][0]);   \
  am[2][0] = fmaf(R.z, WA, am[2][0]); am[3][0] = fmaf(R.w, WA, am[3][0]);   \
  am[0][1] = fmaf(R.x, WB, am[0][1]); am[1][1] = fmaf(R.y, WB, am[1][1]);   \
  am[2][1] = fmaf(R.z, WB, am[2][1]); am[3][1] = fmaf(R.w, WB, am[3][1]);   \
  AO[0][0] = fmaf(R.x, VA, AO[0][0]); AO[1][0] = fmaf(R.y, VA, AO[1][0]);   \
  AO[2][0] = fmaf(R.z, VA, AO[2][0]); AO[3][0] = fmaf(R.w, VA, AO[3][0]);   \
  AO[0][1] = fmaf(R.x, VB, AO[0][1]); AO[1][1] = fmaf(R.y, VB, AO[1][1]);   \
  AO[2][1] = fmaf(R.z, VB, AO[2][1]); AO[3][1] = fmaf(R.w, VB, AO[3][1]);

#define INNER(AO, V1, V2)                                                   \
  _Pragma("unroll 4")                                                       \
  for (int kk = 0; kk < SUBK; kk += 4) {                                    \
    float4 r0 = *(const float4*)(rsc + (kk + 0) * BDIM + bg4);              \
    float4 r1 = *(const float4*)(rsc + (kk + 1) * BDIM + bg4);              \
    float4 r2 = *(const float4*)(rsc + (kk + 2) * BDIM + bg4);              \
    float4 r3 = *(const float4*)(rsc + (kk + 3) * BDIM + bg4);              \
    float4 wa = *(const float4*)(w1a + kk);                                 \
    float4 wb = *(const float4*)(w1b + kk);                                 \
    float4 va = *(const float4*)((V1) + kk);                                \
    float4 vb = *(const float4*)((V2) + kk);                                \
    FMA_J(r0, wa.x, wb.x, va.x, vb.x, AO)                                   \
    FMA_J(r1, wa.y, wb.y, va.y, vb.y, AO)                                   \
    FMA_J(r2, wa.z, wb.z, va.z, vb.z, AO)                                   \
    FMA_J(r3, wa.w, wb.w, va.w, vb.w, AO)                                   \
  }

extern __shared__ float s_mem[];

__global__ void __launch_bounds__(NTHR, 1)
rnn_kernel(const float* __restrict__ W_rec_m1,
           const float* __restrict__ W_rec_pmd,
           const float* __restrict__ W_rec_s1,
           const float* __restrict__ b_m1,
           const float* __restrict__ W_pmd_m1,
           const float* __restrict__ W_s1_m1,
           const float* __restrict__ W_m1_pmd,
           const float* __restrict__ W_out,
           float* __restrict__ out) {
  float* wm1  = s_mem;                       // [4][WM1_STRIDE]  vk: rec_m1 | pmd_m1 | s1_m1
  float* wpmd = wm1 + 4 * WM1_STRIDE;        // [4][WPMD_STRIDE] vk: m1_pmd | rec_pmd
  float* ws1  = wpmd + 4 * WPMD_STRIDE;      // [4][WS1_STRIDE]  vk: rec_s1
  float* rs   = ws1 + 4 * WS1_STRIDE;        // [8 warps][2][SUBK][BDIM]
  float* part = rs + 8 * 2 * RS_SUB;         // [8][BDIM][PROW]

  const int cta = blockIdx.x;
  const int tid = threadIdx.x;
  const int nbase = cta * 4;

  // cache this CTA's weight column slices in SMEM for the whole run
  for (int i = tid; i < 4 * NDIM; i += NTHR) {
    int slot = i >> 9;
    int k = i & 511;
    int n = nbase + slot;
    wm1[slot * WM1_STRIDE + k]          = W_rec_m1[n * NDIM + k];
    wm1[slot * WM1_STRIDE + 512 + k]    = W_pmd_m1[n * NDIM + k];
    wm1[slot * WM1_STRIDE + 1024 + k]   = W_s1_m1[n * NDIM + k];
    wpmd[slot * WPMD_STRIDE + k]        = W_m1_pmd[n * NDIM + k];
    wpmd[slot * WPMD_STRIDE + 512 + k]  = W_rec_pmd[n * NDIM + k];
    ws1[slot * WS1_STRIDE + k]          = W_rec_s1[n * NDIM + k];
  }

  // compute-role mapping: warp owns 192 virtual-k; halves own col pairs; bg owns 4 b-rows
  const int warp = tid >> 5;
  const int lane = tid & 31;
  const int cg = (tid >> 4) & 1;
  const int bg4 = (tid & 15) * 4;
  const int kbase = warp * KSLICE;
  const int ca = cg * 2, cb = cg * 2 + 1;
  float* rs0 = rs + warp * 2 * RS_SUB;

  // state-role mapping: thread owns cell (b, col)
  const int b = tid >> 2;
  const int slot = tid & 3;
  const int col = nbase + slot;
  const float bias_m1 = b_m1[col];
  const float a = 0.1f;
  const float oma = 1.0f - a;
  float x_m1 = 0.0f, x_pmd = 0.0f, x_s1 = 0.0f;
  __syncthreads();

  for (int t = 1; t <= TSTEPS; t++) {
    const unsigned need = (unsigned)(t - 1);
    const float u_pmd = __ldg(&g_U[0][t - 1][b][col]);
    const float u_s1  = __ldg(&g_U[1][t - 1][b][col]);

    const float* rprev = &g_r[(t - 1) & 1][0][0];   // [k][b]

    // prime first two sub-chunks, gated on their 8-CTA producer sets
    wait_prod2(kbase, kbase + SUBK, need, lane);
    cp_sub(rs0, rprev + (size_t)kbase * BDIM, lane);
    asm volatile("cp.async.commit_group;\n" ::: "memory");
    cp_sub(rs0 + RS_SUB, rprev + (size_t)(kbase + SUBK) * BDIM, lane);
    asm volatile("cp.async.commit_group;\n" ::: "memory");

    float am[4][2] = {{0.f, 0.f}, {0.f, 0.f}, {0.f, 0.f}, {0.f, 0.f}};
    float ap[4][2] = {{0.f, 0.f}, {0.f, 0.f}, {0.f, 0.f}, {0.f, 0.f}};
    float as_[4][2] = {{0.f, 0.f}, {0.f, 0.f}, {0.f, 0.f}, {0.f, 0.f}};

#pragma unroll 1
    for (int s = 0; s < NSUB; s++) {
      if (s < NSUB - 1) { asm volatile("cp.async.wait_group 1;\n" ::: "memory"); }
      else              { asm volatile("cp.async.wait_group 0;\n" ::: "memory"); }

      const int k0 = kbase + s * SUBK;
      const float* rsc = rs0 + (s & 1) * RS_SUB;
      const float* w1a = wm1 + ca * WM1_STRIDE + k0;
      const float* w1b = wm1 + cb * WM1_STRIDE + k0;
      if (k0 < 1024) {   // sub-chunks never straddle the 1024 boundary
        const float* v1 = wpmd + ca * WPMD_STRIDE + k0;
        const float* v2 = wpmd + cb * WPMD_STRIDE + k0;
        INNER(ap, v1, v2)
      } else {
        const float* v1 = ws1 + ca * WS1_STRIDE + (k0 - 1024);
        const float* v2 = ws1 + cb * WS1_STRIDE + (k0 - 1024);
        INNER(as_, v1, v2)
      }
      if (s + 2 < NSUB) {
        wait_prod(k0 + 2 * SUBK, need, lane);
        cp_sub(rs0 + (s & 1) * RS_SUB, rprev + (size_t)(k0 + 2 * SUBK) * BDIM, lane);
        asm volatile("cp.async.commit_group;\n" ::: "memory");
      }
    }

    // write k-slice partials
    {
      float* p0 = part + warp * PPLANE + bg4 * PROW;
#pragma unroll
      for (int row = 0; row < 4; row++) {
        float* p = p0 + row * PROW;
        p[ca]     = am[row][0];  p[cb]     = am[row][1];
        p[4 + ca] = ap[row][0];  p[4 + cb] = ap[row][1];
        p[8 + ca] = as_[row][0]; p[8 + cb] = as_[row][1];
      }
    }
    __syncthreads();

    // reduce over 8 k-slices + leaky update + tanh (state role)
    float sm = 0.f, sp = 0.f, ss = 0.f;
#pragma unroll
    for (int q = 0; q < 8; q++) {
      const float* p = part + q * PPLANE + b * PROW;
      sm += p[slot]; sp += p[4 + slot]; ss += p[8 + slot];
    }
    x_m1  = oma * x_m1  + a * (sm + bias_m1);
    x_pmd = oma * x_pmd + a * (sp + u_pmd);
    x_s1  = oma * x_s1  + a * (ss + u_s1);
    const float r_m1  = tanhf(x_m1);
    const float r_pmd = tanhf(x_pmd);
    const float r_s1v = tanhf(x_s1);

    float* rn = &g_r[t & 1][0][0];
    rn[col * BDIM + b]          = r_m1;
    rn[(512 + col) * BDIM + b]  = r_pmd;
    rn[(1024 + col) * BDIM + b] = r_s1v;
    g_rm1h[t - 1][b][col] = r_m1;

    // ---- publish: this CTA's step-t slice is globally visible ----
    __threadfence();
    __syncthreads();
    if (tid == 0) *(volatile unsigned*)&g_flag[cta * FLAG_STRIDE] = (unsigned)t;
    // no global barrier: consumers gate per-chunk on producer flags (skew <= 1 step,
    // so the 2-buffer r ping-pong stays race-free)
  }

  // ---- one-shot global barrier before the output phase (g_rm1h fully written) ----
  __threadfence();
  __syncthreads();
  if (tid == 0) {
    unsigned prev = atomicAdd(&g_count, 1u);
    if (prev == (unsigned)NCTA - 1u) {
      __threadfence();
      *((volatile unsigned*)&g_gen) = 1u;
    } else {
      while (*((volatile unsigned*)&g_gen) < 1u) { }
      __threadfence();
    }
  }
  __syncthreads();

  // ---------------- fused output projection: out[t] = r_m1[t] @ W_out^T ----------------
  float* wo = part;   // reuse partials area: ODIM*WOS = 5200 <= 6656 floats
  for (int i = tid; i < ODIM * NDIM; i += NTHR)
    wo[(i / NDIM) * WOS + (i % NDIM)] = W_out[i];
  __syncthreads();

  for (int t = cta; t < TSTEPS; t += NCTA) {
    const float* R = &g_rm1h[t][0][0];
    for (int idx = tid; idx < BDIM * ODIM; idx += NTHR) {
      int bb = idx / ODIM, o = idx % ODIM;
      const float* r = R + bb * NDIM;
      const float* w = wo + o * WOS;
      float s0 = 0.f, s1 = 0.f, s2 = 0.f, s3 = 0.f;
#pragma unroll 8
      for (int k = 0; k < NDIM; k += 16) {
        float4 r0 = *(const float4*)(r + k);
        float4 r1 = *(const float4*)(r + k + 4);
        float4 r2 = *(const float4*)(r + k + 8);
        float4 r3 = *(const float4*)(r + k + 12);
        float4 w0 = *(const float4*)(w + k);
        float4 w1 = *(const float4*)(w + k + 4);
        float4 w2 = *(const float4*)(w + k + 8);
        float4 w3 = *(const float4*)(w + k + 12);
        s0 += r0.x * w0.x + r0.y * w0.y + r0.z * w0.z + r0.w * w0.w;
        s1 += r1.x * w1.x + r1.y * w1.y + r1.z * w1.z + r1.w * w1.w;
        s2 += r2.x * w2.x + r2.y * w2.y + r2.z * w2.z + r2.w * w2.w;
        s3 += r3.x * w3.x + r3.y * w3.y + r3.z * w3.z + r3.w * w3.w;
      }
      out[t * (BDIM * ODIM) + idx] = (s0 + s1) + (s2 + s3);
    }
  }
}

// ---------------- launch ----------------
extern "C" void kernel_launch(void* const* d_in, const int* in_sizes, int n_in,
                              void* d_out, int out_size) {
  (void)in_sizes; (void)n_in; (void)out_size;
  const float* X         = (const float*)d_in[0];
  const float* W_rec_m1  = (const float*)d_in[1];
  const float* W_rec_pmd = (const float*)d_in[2];
  const float* W_rec_s1  = (const float*)d_in[3];
  const float* b_m1      = (const float*)d_in[4];
  const float* b_pmd     = (const float*)d_in[5];
  const float* b_s1      = (const float*)d_in[6];
  const float* W_pmd_m1  = (const float*)d_in[7];
  const float* W_s1_m1   = (const float*)d_in[8];
  const float* W_m1_pmd  = (const float*)d_in[9];
  const float* W_in_pmd  = (const float*)d_in[10];
  const float* W_in_s1   = (const float*)d_in[11];
  const float* W_out     = (const float*)d_in[12];
  float* out = (float*)d_out;

  dim3 gA(TSTEPS, 32);
  setup_kernel<<<gA, NTHR>>>(X, W_in_pmd, W_in_s1, b_pmd, b_s1);

  const int smem_bytes =
      (4 * WM1_STRIDE + 4 * WPMD_STRIDE + 4 * WS1_STRIDE + 8 * 2 * RS_SUB + 8 * PPLANE) *
      (int)sizeof(float);   // 207,232 B
  cudaFuncSetAttribute(rnn_kernel, cudaFuncAttributeMaxDynamicSharedMemorySize, smem_bytes);
  rnn_kernel<<<NCTA, NTHR, smem_bytes>>>(W_rec_m1, W_rec_pmd, W_rec_s1, b_m1,
                                         W_pmd_m1, W_s1_m1, W_m1_pmd, W_out, out);
}

// round 16
// speedup vs baseline: 1.2630x; 1.0505x over previous
#include <cuda_runtime.h>
#include <cuda_bf16.h>

// Problem dims
#define TSTEPS 499
#define BDIM 64
#define NDIM 512
#define DDIM 100
#define ODIM 10
#define KCAT 1536

// RNN kernel config
#define NCTA 128
#define NTHR 256
#define KSLICE 192          // virtual-k per warp (8 warps x 192 = 1536)
#define SUBK 32             // k per sub-chunk (region boundaries k=512/1024 are multiples: aligned)
#define NSUB 6
#define RS_SUB (SUBK * BDIM)      // 2048 floats = 8KB

// SMEM weight strides (floats), %32==8 -> col slices on distinct bank groups
#define WM1_STRIDE 1544
#define WPMD_STRIDE 1032
#define WS1_STRIDE 520
// partials: [8 warps][64 b][13] (12 used: m1 c0..3 | pmd c0..3 | s1 c0..3)
#define PROW 13
#define PPLANE (BDIM * PROW)
// W_out smem stride for output phase (reuses partials area)
#define WOS 520

// per-CTA publish flags, spread 256B to distribute poll traffic over LTS partitions
#define FLAG_STRIDE 64      // unsigneds = 256B

// ---------------- device scratch (static; no allocations) ----------------
__device__ float g_U[2][TSTEPS][BDIM][NDIM];   // [0]=pmd drive, [1]=s1 drive (bias folded)
__device__ float g_r[2][KCAT][BDIM];           // ping-pong rcat, k-major [k][b]
__device__ float g_rm1h[TSTEPS][BDIM][NDIM];   // r_m1 history for deferred output GEMM
__device__ unsigned g_flag[NCTA * FLAG_STRIDE];// per-CTA step-publication flags (monotone)
__device__ unsigned g_count;                   // final-barrier arrival counter
__device__ unsigned g_gen;                     // final-barrier release

// ---------------- setup: init fold + time-parallel input projections ----------------
__global__ void setup_kernel(const float* __restrict__ X,
                             const float* __restrict__ W_in_pmd,
                             const float* __restrict__ W_in_s1,
                             const float* __restrict__ b_pmd,
                             const float* __restrict__ b_s1) {
  __shared__ __align__(16) float Xs[32][DDIM];
  __shared__ __align__(16) float Ws[64][DDIM];
  const int tIdx = blockIdx.x;
  const int y    = blockIdx.y;
  const int tid  = threadIdx.x;

  // folded init (rnn_kernel launches after this kernel completes)
  if (y == 0) {
    if (tIdx == 0 && tid == 0) { g_gen = 0u; g_count = 0u; }
    if (tIdx < 96) {
      float* r0 = &g_r[0][0][0];  // 98304 floats / 96 blocks = 1024 each
      int base = tIdx * 1024;
#pragma unroll
      for (int j = 0; j < 4; j++) r0[base + tid + j * NTHR] = 0.0f;
    } else {
      g_flag[(tIdx - 96) * NTHR + tid] = 0u;   // 32 blocks x 256 = 8192 = NCTA*FLAG_STRIDE
    }
  }

  const int reg   = y >> 4;
  const int bhalf = (y >> 3) & 1;
  const int nblk  = y & 7;
  const int b0 = bhalf * 32;
  const int n0 = nblk * 64;
  const float* W    = reg ? W_in_s1 : W_in_pmd;
  const float* bias = reg ? b_s1    : b_pmd;
  const float* Xt = X + (size_t)(tIdx + 1) * (BDIM * DDIM);

  for (int i = tid; i < 32 * DDIM; i += NTHR)
    Xs[i / DDIM][i % DDIM] = Xt[(b0 + i / DDIM) * DDIM + (i % DDIM)];
  for (int i = tid; i < 64 * DDIM; i += NTHR)
    Ws[i / DDIM][i % DDIM] = W[(n0 + i / DDIM) * DDIM + (i % DDIM)];
  __syncthreads();

  const int ty = tid >> 4, tx = tid & 15;
  const int bb = 2 * ty, nn = 4 * tx;
  float acc[2][4];
#pragma unroll
  for (int j = 0; j < 4; j++) {
    float bv = bias[n0 + nn + j];
    acc[0][j] = bv; acc[1][j] = bv;
  }
#pragma unroll
  for (int k = 0; k < DDIM; k += 4) {
    float4 x0 = *(const float4*)&Xs[bb][k];
    float4 x1 = *(const float4*)&Xs[bb + 1][k];
#pragma unroll
    for (int j = 0; j < 4; j++) {
      float4 wv = *(const float4*)&Ws[nn + j][k];
      acc[0][j] += x0.x * wv.x + x0.y * wv.y + x0.z * wv.z + x0.w * wv.w;
      acc[1][j] += x1.x * wv.x + x1.y * wv.y + x1.z * wv.z + x1.w * wv.w;
    }
  }
#pragma unroll
  for (int i2 = 0; i2 < 2; i2++)
#pragma unroll
    for (int j = 0; j < 4; j++)
      g_U[reg][tIdx][b0 + bb + i2][n0 + nn + j] = acc[i2][j];
}

// ---------------- persistent serial RNN core (+ fused output projection) ----------------
__device__ __forceinline__ void cp_sub(float* dst, const float* src, int lane) {
  // contiguous 8KB (32 k-rows x 64 b) copy, 16 float4 per lane; .cg bypasses L1
#pragma unroll
  for (int j = 0; j < 16; j++) {
    int o = (lane + j * 32) * 4;
    unsigned s = (unsigned)__cvta_generic_to_shared(dst + o);
    asm volatile("cp.async.cg.shared.global [%0], [%1], 16;\n" :: "r"(s), "l"(src + o) : "memory");
  }
}

// wait until the 8 producer CTAs of chunk vk0 have published step `need`
__device__ __forceinline__ void wait_prod(int vk0, unsigned need, int lane) {
  if (need == 0u) return;                      // initial state (zeros) always ready
  const int base = (vk0 & 511) >> 2;
  for (;;) {
    unsigned f = need;
    if (lane < 8) f = *(volatile unsigned*)&g_flag[(base + lane) * FLAG_STRIDE];
    if (__all_sync(0xffffffffu, f >= need)) return;
  }
}

// combined wait for the two primed chunks (lanes 0-7: chunk A, lanes 8-15: chunk B)
__device__ __forceinline__ void wait_prod2(int vkA, int vkB, unsigned need, int lane) {
  if (need == 0u) return;
  const int baseA = (vkA & 511) >> 2;
  const int baseB = (vkB & 511) >> 2;
  for (;;) {
    unsigned f = need;
    if (lane < 8)       f = *(volatile unsigned*)&g_flag[(baseA + lane) * FLAG_STRIDE];
    else if (lane < 16) f = *(volatile unsigned*)&g_flag[(baseB + lane - 8) * FLAG_STRIDE];
    if (__all_sync(0xffffffffu, f >= need)) return;
  }
}

#define FMA_J(R, WA, WB, VA, VB, AO)                                        \
  am[0][0] = fmaf(R.x, WA, am[0][0]); am[1][0] = fmaf(R.y, WA, am[1][0]);   \
  am[2][0] = fmaf(R.z, WA, am[2][0]); am[3][0] = fmaf(R.w, WA, am[3][0]);   \
  am[0][1] = fmaf(R.x, WB, am[0][1]); am[1][1] = fmaf(R.y, WB, am[1][1]);   \
  am[2][1] = fmaf(R.z, WB, am[2][1]); am[3][1] = fmaf(R.w, WB, am[3][1]);   \
  AO[0][0] = fmaf(R.x, VA, AO[0][0]); AO[1][0] = fmaf(R.y, VA, AO[1][0]);   \
  AO[2][0] = fmaf(R.z, VA, AO[2][0]); AO[3][0] = fmaf(R.w, VA, AO[3][0]);   \
  AO[0][1] = fmaf(R.x, VB, AO[0][1]); AO[1][1] = fmaf(R.y, VB, AO[1][1]);   \
  AO[2][1] = fmaf(R.z, VB, AO[2][1]); AO[3][1] = fmaf(R.w, VB, AO[3][1]);

#define INNER(AO, V1, V2)                                                   \
  _Pragma("unroll 4")                                                       \
  for (int kk = 0; kk < SUBK; kk += 4) {                                    \
    float4 r0 = *(const float4*)(rsc + (kk + 0) * BDIM + bg4);              \
    float4 r1 = *(const float4*)(rsc + (kk + 1) * BDIM + bg4);              \
    float4 r2 = *(const float4*)(rsc + (kk + 2) * BDIM + bg4);              \
    float4 r3 = *(const float4*)(rsc + (kk + 3) * BDIM + bg4);              \
    float4 wa = *(const float4*)(w1a + kk);                                 \
    float4 wb = *(const float4*)(w1b + kk);                                 \
    float4 va = *(const float4*)((V1) + kk);                                \
    float4 vb = *(const float4*)((V2) + kk);                                \
    FMA_J(r0, wa.x, wb.x, va.x, vb.x, AO)                                   \
    FMA_J(r1, wa.y, wb.y, va.y, vb.y, AO)                                   \
    FMA_J(r2, wa.z, wb.z, va.z, vb.z, AO)                                   \
    FMA_J(r3, wa.w, wb.w, va.w, vb.w, AO)                                   \
  }

extern __shared__ float s_mem[];

__global__ void __launch_bounds__(NTHR, 1)
rnn_kernel(const float* __restrict__ W_rec_m1,
           const float* __restrict__ W_rec_pmd,
           const float* __restrict__ W_rec_s1,
           const float* __restrict__ b_m1,
           const float* __restrict__ W_pmd_m1,
           const float* __restrict__ W_s1_m1,
           const float* __restrict__ W_m1_pmd,
           const float* __restrict__ W_out,
           float* __restrict__ out) {
  float* wm1  = s_mem;                       // [4][WM1_STRIDE]  vk: rec_m1 | pmd_m1 | s1_m1
  float* wpmd = wm1 + 4 * WM1_STRIDE;        // [4][WPMD_STRIDE] vk: m1_pmd | rec_pmd
  float* ws1  = wpmd + 4 * WPMD_STRIDE;      // [4][WS1_STRIDE]  vk: rec_s1
  float* rs   = ws1 + 4 * WS1_STRIDE;        // [8 warps][2][SUBK][BDIM]
  float* part = rs + 8 * 2 * RS_SUB;         // [8][BDIM][PROW]

  const int cta = blockIdx.x;
  const int tid = threadIdx.x;
  const int nbase = cta * 4;

  // cache this CTA's weight column slices in SMEM for the whole run
  for (int i = tid; i < 4 * NDIM; i += NTHR) {
    int slot = i >> 9;
    int k = i & 511;
    int n = nbase + slot;
    wm1[slot * WM1_STRIDE + k]          = W_rec_m1[n * NDIM + k];
    wm1[slot * WM1_STRIDE + 512 + k]    = W_pmd_m1[n * NDIM + k];
    wm1[slot * WM1_STRIDE + 1024 + k]   = W_s1_m1[n * NDIM + k];
    wpmd[slot * WPMD_STRIDE + k]        = W_m1_pmd[n * NDIM + k];
    wpmd[slot * WPMD_STRIDE + 512 + k]  = W_rec_pmd[n * NDIM + k];
    ws1[slot * WS1_STRIDE + k]          = W_rec_s1[n * NDIM + k];
  }

  // compute-role mapping: warp owns 192 virtual-k; halves own col pairs; bg owns 4 b-rows
  const int warp = tid >> 5;
  const int lane = tid & 31;
  const int cg = (tid >> 4) & 1;
  const int bg4 = (tid & 15) * 4;
  const int kbase = warp * KSLICE;
  const int ca = cg * 2, cb = cg * 2 + 1;
  float* rs0 = rs + warp * 2 * RS_SUB;

  // state-role mapping: thread owns cell (b, col)
  const int b = tid >> 2;
  const int slot = tid & 3;
  const int col = nbase + slot;
  const float bias_m1 = b_m1[col];
  const float a = 0.1f;
  const float oma = 1.0f - a;
  float x_m1 = 0.0f, x_pmd = 0.0f, x_s1 = 0.0f;
  __syncthreads();

  for (int t = 1; t <= TSTEPS; t++) {
    const unsigned need = (unsigned)(t - 1);
    const float u_pmd = __ldg(&g_U[0][t - 1][b][col]);
    const float u_s1  = __ldg(&g_U[1][t - 1][b][col]);

    const float* rprev = &g_r[(t - 1) & 1][0][0];   // [k][b]

    // prime first two sub-chunks, gated on their 8-CTA producer sets
    wait_prod2(kbase, kbase + SUBK, need, lane);
    cp_sub(rs0, rprev + (size_t)kbase * BDIM, lane);
    asm volatile("cp.async.commit_group;\n" ::: "memory");
    cp_sub(rs0 + RS_SUB, rprev + (size_t)(kbase + SUBK) * BDIM, lane);
    asm volatile("cp.async.commit_group;\n" ::: "memory");

    float am[4][2] = {{0.f, 0.f}, {0.f, 0.f}, {0.f, 0.f}, {0.f, 0.f}};
    float ap[4][2] = {{0.f, 0.f}, {0.f, 0.f}, {0.f, 0.f}, {0.f, 0.f}};
    float as_[4][2] = {{0.f, 0.f}, {0.f, 0.f}, {0.f, 0.f}, {0.f, 0.f}};

#pragma unroll 1
    for (int s = 0; s < NSUB; s++) {
      if (s < NSUB - 1) { asm volatile("cp.async.wait_group 1;\n" ::: "memory"); }
      else              { asm volatile("cp.async.wait_group 0;\n" ::: "memory"); }

      const int k0 = kbase + s * SUBK;
      const float* rsc = rs0 + (s & 1) * RS_SUB;
      const float* w1a = wm1 + ca * WM1_STRIDE + k0;
      const float* w1b = wm1 + cb * WM1_STRIDE + k0;
      if (k0 < 1024) {   // sub-chunks never straddle the 1024 boundary
        const float* v1 = wpmd + ca * WPMD_STRIDE + k0;
        const float* v2 = wpmd + cb * WPMD_STRIDE + k0;
        INNER(ap, v1, v2)
      } else {
        const float* v1 = ws1 + ca * WS1_STRIDE + (k0 - 1024);
        const float* v2 = ws1 + cb * WS1_STRIDE + (k0 - 1024);
        INNER(as_, v1, v2)
      }
      if (s + 2 < NSUB) {
        wait_prod(k0 + 2 * SUBK, need, lane);
        cp_sub(rs0 + (s & 1) * RS_SUB, rprev + (size_t)(k0 + 2 * SUBK) * BDIM, lane);
        asm volatile("cp.async.commit_group;\n" ::: "memory");
      }
    }

    // write k-slice partials
    {
      float* p0 = part + warp * PPLANE + bg4 * PROW;
#pragma unroll
      for (int row = 0; row < 4; row++) {
        float* p = p0 + row * PROW;
        p[ca]     = am[row][0];  p[cb]     = am[row][1];
        p[4 + ca] = ap[row][0];  p[4 + cb] = ap[row][1];
        p[8 + ca] = as_[row][0]; p[8 + cb] = as_[row][1];
      }
    }
    __syncthreads();

    // reduce over 8 k-slices + leaky update + tanh (state role)
    float sm = 0.f, sp = 0.f, ss = 0.f;
#pragma unroll
    for (int q = 0; q < 8; q++) {
      const float* p = part + q * PPLANE + b * PROW;
      sm += p[slot]; sp += p[4 + slot]; ss += p[8 + slot];
    }
    x_m1  = oma * x_m1  + a * (sm + bias_m1);
    x_pmd = oma * x_pmd + a * (sp + u_pmd);
    x_s1  = oma * x_s1  + a * (ss + u_s1);
    const float r_m1  = tanhf(x_m1);
    const float r_pmd = tanhf(x_pmd);
    const float r_s1v = tanhf(x_s1);

    float* rn = &g_r[t & 1][0][0];
    rn[col * BDIM + b]          = r_m1;
    rn[(512 + col) * BDIM + b]  = r_pmd;
    rn[(1024 + col) * BDIM + b] = r_s1v;

    // ---- publish ASAP: syncthreads orders all threads' r-stores before tid0's
    // cumulative gpu fence; one membar instead of 256. ----
    __syncthreads();
    if (tid == 0) {
      __threadfence();
      *(volatile unsigned*)&g_flag[cta * FLAG_STRIDE] = (unsigned)t;
    }

    // history store off the critical path (only read after the final barrier)
    g_rm1h[t - 1][b][col] = r_m1;
  }

  // ---- one-shot global barrier before the output phase (g_rm1h fully written) ----
  __threadfence();
  __syncthreads();
  if (tid == 0) {
    unsigned prev = atomicAdd(&g_count, 1u);
    if (prev == (unsigned)NCTA - 1u) {
      __threadfence();
      *((volatile unsigned*)&g_gen) = 1u;
    } else {
      while (*((volatile unsigned*)&g_gen) < 1u) { }
      __threadfence();
    }
  }
  __syncthreads();

  // ---------------- fused output projection: out[t] = r_m1[t] @ W_out^T ----------------
  float* wo = part;   // reuse partials area: ODIM*WOS = 5200 <= 6656 floats
  for (int i = tid; i < ODIM * NDIM; i += NTHR)
    wo[(i / NDIM) * WOS + (i % NDIM)] = W_out[i];
  __syncthreads();

  for (int t = cta; t < TSTEPS; t += NCTA) {
    const float* R = &g_rm1h[t][0][0];
    for (int idx = tid; idx < BDIM * ODIM; idx += NTHR) {
      int bb = idx / ODIM, o = idx % ODIM;
      const float* r = R + bb * NDIM;
      const float* w = wo + o * WOS;
      float s0 = 0.f, s1 = 0.f, s2 = 0.f, s3 = 0.f;
#pragma unroll 8
      for (int k = 0; k < NDIM; k += 16) {
        float4 r0 = *(const float4*)(r + k);
        float4 r1 = *(const float4*)(r + k + 4);
        float4 r2 = *(const float4*)(r + k + 8);
        float4 r3 = *(const float4*)(r + k + 12);
        float4 w0 = *(const float4*)(w + k);
        float4 w1 = *(const float4*)(w + k + 4);
        float4 w2 = *(const float4*)(w + k + 8);
        float4 w3 = *(const float4*)(w + k + 12);
        s0 += r0.x * w0.x + r0.y * w0.y + r0.z * w0.z + r0.w * w0.w;
        s1 += r1.x * w1.x + r1.y * w1.y + r1.z * w1.z + r1.w * w1.w;
        s2 += r2.x * w2.x + r2.y * w2.y + r2.z * w2.z + r2.w * w2.w;
        s3 += r3.x * w3.x + r3.y * w3.y + r3.z * w3.z + r3.w * w3.w;
      }
      out[t * (BDIM * ODIM) + idx] = (s0 + s1) + (s2 + s3);
    }
  }
}

// ---------------- launch ----------------
extern "C" void kernel_launch(void* const* d_in, const int* in_sizes, int n_in,
                              void* d_out, int out_size) {
  (void)in_sizes; (void)n_in; (void)out_size;
  const float* X         = (const float*)d_in[0];
  const float* W_rec_m1  = (const float*)d_in[1];
  const float* W_rec_pmd = (const float*)d_in[2];
  const float* W_rec_s1  = (const float*)d_in[3];
  const float* b_m1      = (const float*)d_in[4];
  const float* b_pmd     = (const float*)d_in[5];
  const float* b_s1      = (const float*)d_in[6];
  const float* W_pmd_m1  = (const float*)d_in[7];
  const float* W_s1_m1   = (const float*)d_in[8];
  const float* W_m1_pmd  = (const float*)d_in[9];
  const float* W_in_pmd  = (const float*)d_in[10];
  const float* W_in_s1   = (const float*)d_in[11];
  const float* W_out     = (const float*)d_in[12];
  float* out = (float*)d_out;

  dim3 gA(TSTEPS, 32);
  setup_kernel<<<gA, NTHR>>>(X, W_in_pmd, W_in_s1, b_pmd, b_s1);

  const int smem_bytes =
      (4 * WM1_STRIDE + 4 * WPMD_STRIDE + 4 * WS1_STRIDE + 8 * 2 * RS_SUB + 8 * PPLANE) *
      (int)sizeof(float);   // 207,232 B
  cudaFuncSetAttribute(rnn_kernel, cudaFuncAttributeMaxDynamicSharedMemorySize, smem_bytes);
  rnn_kernel<<<NCTA, NTHR, smem_bytes>>>(W_rec_m1, W_rec_pmd, W_rec_s1, b_m1,
                                         W_pmd_m1, W_s1_m1, W_m1_pmd, W_out, out);
}